// round 15
// baseline (speedup 1.0000x reference)
#include <cuda_runtime.h>
#include <cuda_bf16.h>
#include <cuda_fp16.h>
#include <math.h>
#include <stdint.h>

#define NT 2048
#define TT 1024
#define DD 768
#define FF 3072
#define HH 12
#define HD 64
#define LL 4
#define VV 50257
#define D3 2304
#define VP 50304
#define K2D 384
#define K2F 1536
#define NSPL 8

// ---------------- scratch ----------------
__device__ float    g_x[NT * DD];
__device__ float    g_qkv[NT * D3];   // also split-K partial buffer [3][NT][DD]
__device__ uint32_t g_hF[NT * K2D];
__device__ uint32_t g_atF[NT * K2D];
__device__ uint32_t g_ffF[NT * K2F];
__device__ float    g_oP[NSPL * NT * HH * 64];      // attention o-partials
__device__ float2   g_attms[NSPL * NT * HH];        // (m, ssum)
// weights n-major [N][K/2] fp16-pair words, scaled x256, hi/lo
__device__ uint32_t g_wq_h[LL * D3 * K2D], g_wq_l[LL * D3 * K2D];
__device__ uint32_t g_wp_h[LL * DD * K2D], g_wp_l[LL * DD * K2D];
__device__ uint32_t g_wf_h[LL * FF * K2D], g_wf_l[LL * FF * K2D];
__device__ uint32_t g_w2_h[LL * DD * K2F], g_w2_l[LL * DD * K2F];
__device__ uint32_t g_wh_h[VP * K2D];

// ---------------- helpers ----------------
__device__ __forceinline__ uint32_t pkh(float x, float y) {
    __half hx = __float2half_rn(x), hy = __float2half_rn(y);
    return ((uint32_t)__half_as_ushort(hy) << 16) | (uint32_t)__half_as_ushort(hx);
}
__device__ __forceinline__ void cvt2h(float x, float y, uint32_t& hi, uint32_t& lo) {
    __half hx = __float2half_rn(x), hy = __float2half_rn(y);
    hi = ((uint32_t)__half_as_ushort(hy) << 16) | (uint32_t)__half_as_ushort(hx);
    lo = pkh(x - __half2float(hx), y - __half2float(hy));
}
__device__ __forceinline__ void cpa16(uint32_t d, const void* s) {
    asm volatile("cp.async.cg.shared.global [%0], [%1], 16;" :: "r"(d), "l"(s));
}
__device__ __forceinline__ void ldsm4(uint32_t* r, uint32_t a) {
    asm volatile("ldmatrix.sync.aligned.m8n8.x4.shared.b16 {%0,%1,%2,%3}, [%4];"
                 : "=r"(r[0]), "=r"(r[1]), "=r"(r[2]), "=r"(r[3]) : "r"(a));
}
__device__ __forceinline__ void mmaf16(float* c, const uint32_t* a, uint32_t b0, uint32_t b1) {
    asm volatile("mma.sync.aligned.m16n8k16.row.col.f32.f16.f16.f32 "
                 "{%0,%1,%2,%3}, {%4,%5,%6,%7}, {%8,%9}, {%0,%1,%2,%3};\n"
                 : "+f"(c[0]), "+f"(c[1]), "+f"(c[2]), "+f"(c[3])
                 : "r"(a[0]), "r"(a[1]), "r"(a[2]), "r"(a[3]), "r"(b0), "r"(b1));
}
__device__ __forceinline__ uint64_t f2pk(float x, float y) {
    uint64_t r; asm("mov.b64 %0, {%1,%2};" : "=l"(r) : "f"(x), "f"(y)); return r;
}
__device__ __forceinline__ void f2un(uint64_t v, float& x, float& y) {
    asm("mov.b64 {%0,%1}, %2;" : "=f"(x), "=f"(y) : "l"(v));
}
__device__ __forceinline__ uint64_t fma2(uint64_t a, uint64_t b, uint64_t c) {
    uint64_t d; asm("fma.rn.f32x2 %0, %1, %2, %3;" : "=l"(d) : "l"(a), "l"(b), "l"(c)); return d;
}
__device__ __forceinline__ uint64_t mul2(uint64_t a, uint64_t b) {
    uint64_t d; asm("mul.rn.f32x2 %0, %1, %2;" : "=l"(d) : "l"(a), "l"(b)); return d;
}

// ---------------- packing ----------------
__global__ void pack_w_t(const float* __restrict__ W, uint32_t* __restrict__ Oh,
                         uint32_t* __restrict__ Ol, int K, int N) {
    __shared__ float s[64][33];
    int K2 = K >> 1;
    const float* Wl = W + (size_t)blockIdx.z * K * N;
    uint32_t* OhL = Oh + (size_t)blockIdx.z * N * K2;
    uint32_t* OlL = Ol + (size_t)blockIdx.z * N * K2;
    int k0 = blockIdx.x * 64, n0 = blockIdx.y * 32;
    int rr = threadIdx.x >> 5, cc = threadIdx.x & 31;
    #pragma unroll
    for (int i = 0; i < 8; i++)
        s[rr + i * 8][cc] = Wl[(size_t)(k0 + rr + i * 8) * N + n0 + cc];
    __syncthreads();
    #pragma unroll
    for (int i = 0; i < 4; i++) {
        int n = rr + i * 8;
        uint32_t h, l;
        cvt2h(s[2 * cc][n] * 256.f, s[2 * cc + 1][n] * 256.f, h, l);
        OhL[(size_t)(n0 + n) * K2 + (k0 >> 1) + cc] = h;
        OlL[(size_t)(n0 + n) * K2 + (k0 >> 1) + cc] = l;
    }
}
__global__ void pack_headf(const float* __restrict__ W, uint32_t* __restrict__ Oh) {
    int id = blockIdx.x * 256 + threadIdx.x;
    if (id >= VP * K2D) return;
    int n = id / K2D, kp = id - n * K2D;
    float x = 0.f, y = 0.f;
    if (n < VV) { const float* p = W + (size_t)n * DD + 2 * kp; x = p[0] * 256.f; y = p[1] * 256.f; }
    Oh[id] = pkh(x, y);
}

// ---------------- LN machinery ----------------
__device__ __forceinline__ float blk_sum(float v, float* red) {
    #pragma unroll
    for (int o = 16; o; o >>= 1) v += __shfl_xor_sync(0xffffffffu, v, o);
    if ((threadIdx.x & 31) == 0) red[threadIdx.x >> 5] = v;
    __syncthreads();
    float s = (threadIdx.x < 8) ? red[threadIdx.x] : 0.0f;
    #pragma unroll
    for (int o = 4; o; o >>= 1) s += __shfl_xor_sync(0xffffffffu, s, o);
    if (threadIdx.x == 0) red[0] = s;
    __syncthreads();
    s = red[0];
    __syncthreads();
    return s;
}

__device__ __forceinline__ void ln_body(float* v, float s, float ss, float* vb,
                                        const float* w, const float* b, int row,
                                        uint32_t* PF) {
    float mu = s * (1.0f / DD);
    float r = rsqrtf(ss * (1.0f / DD) - mu * mu + 1e-5f);
    #pragma unroll
    for (int i = 0; i < 3; i++) {
        int c = threadIdx.x + i * 256;
        vb[c] = (v[i] - mu) * r * w[c] + b[c];
    }
    __syncthreads();
    #pragma unroll
    for (int i = 0; i < 2; i++) {
        int p = threadIdx.x + i * 256;
        if (p < K2D)
            PF[(size_t)row * K2D + p] = pkh(vb[2 * p], vb[2 * p + 1]);
    }
}

__global__ void embed_ln_pack(const int* __restrict__ tok, const float* __restrict__ wte,
                              const float* __restrict__ wpe, float* __restrict__ x,
                              const float* __restrict__ w, const float* __restrict__ b,
                              uint32_t* __restrict__ PF) {
    __shared__ float vb[DD];
    __shared__ float red[32];
    int row = blockIdx.x, t = tok[row];
    const float* we = wte + (size_t)t * DD;
    const float* wp = wpe + (size_t)(row & (TT - 1)) * DD;
    float v[3], s = 0.f, ss = 0.f;
    #pragma unroll
    for (int i = 0; i < 3; i++) {
        int c = threadIdx.x + i * 256;
        v[i] = we[c] + wp[c];
        x[(size_t)row * DD + c] = v[i];
        s += v[i]; ss += v[i] * v[i];
    }
    s = blk_sum(s, red); ss = blk_sum(ss, red);
    ln_body(v, s, ss, vb, w, b, row, PF);
}

__global__ void red_ln_pack(const float* __restrict__ P, const float* __restrict__ bias,
                            float* __restrict__ x, const float* __restrict__ w,
                            const float* __restrict__ b, uint32_t* __restrict__ PF) {
    __shared__ float vb[DD];
    __shared__ float red[32];
    int row = blockIdx.x;
    float v[3], s = 0.f, ss = 0.f;
    #pragma unroll
    for (int i = 0; i < 3; i++) {
        int c = threadIdx.x + i * 256;
        size_t idx = (size_t)row * DD + c;
        float t = x[idx] + bias[c] + P[idx] + P[(size_t)NT * DD + idx] + P[2 * (size_t)NT * DD + idx];
        x[idx] = t;
        v[i] = t; s += t; ss += t * t;
    }
    s = blk_sum(s, red); ss = blk_sum(ss, red);
    ln_body(v, s, ss, vb, w, b, row, PF);
}

// ---------------- attention: split-KV (8-way) ----------------
// grid (TT/128, HH*NSPL, 2): blockIdx.y = h*NSPL + split.
__global__ void __launch_bounds__(128)
attn_split(const float* __restrict__ qkv, float* __restrict__ oP,
           float2* __restrict__ msP) {
    extern __shared__ __align__(16) unsigned sm_dyn[];
    float* Ks = (float*)sm_dyn;
    float* Vs = Ks + 4096;
    float* sc = Vs + 4096;
    int tid = threadIdx.x;
    int qt = blockIdx.x;
    int h = blockIdx.y >> 3, split = blockIdx.y & 7;
    int b = blockIdx.z;
    int qpos = qt * 128 + tid;
    const float* base = qkv + (size_t)b * TT * D3;
    uint64_t q2[32], o2[32];
    {
        const float* qp = base + (size_t)qpos * D3 + h * HD;
        #pragma unroll
        for (int j = 0; j < 32; j++) q2[j] = f2pk(qp[2 * j], qp[2 * j + 1]);
    }
    #pragma unroll
    for (int j = 0; j < 32; j++) o2[j] = 0ull;
    float m = -1e30f, ssum = 0.f;
    int nkt = (qt + 1) * 2;
    for (int kt = split; kt < nkt; kt += NSPL) {
        int k0 = kt * 64;
        __syncthreads();
        #pragma unroll
        for (int i = 0; i < 8; i++) {
            int idx = (i * 128 + tid) * 4;
            int kk = idx >> 6, e = idx & 63;
            const float* rowp = base + (size_t)(k0 + kk) * D3 + h * HD + e;
            *(float4*)(Ks + idx) = *(const float4*)(rowp + DD);
            *(float4*)(Vs + idx) = *(const float4*)(rowp + 2 * DD);
        }
        __syncthreads();
        float tm = -1e30f;
        for (int kk = 0; kk < 64; kk++) {
            const uint64_t* kr = (const uint64_t*)(Ks + (kk << 6));
            uint64_t a0 = 0ull, a1 = 0ull, a2 = 0ull, a3 = 0ull;
            #pragma unroll
            for (int j = 0; j < 32; j += 4) {
                a0 = fma2(q2[j], kr[j], a0);
                a1 = fma2(q2[j + 1], kr[j + 1], a1);
                a2 = fma2(q2[j + 2], kr[j + 2], a2);
                a3 = fma2(q2[j + 3], kr[j + 3], a3);
            }
            float x0, y0, x1, y1, x2, y2, x3, y3;
            f2un(a0, x0, y0); f2un(a1, x1, y1); f2un(a2, x2, y2); f2un(a3, x3, y3);
            float sv = (((x0 + y0) + (x1 + y1)) + ((x2 + y2) + (x3 + y3))) * 0.125f;
            if (k0 + kk > qpos) sv = -1e30f;
            sc[kk * 128 + tid] = sv;
            tm = fmaxf(tm, sv);
        }
        float mn = fmaxf(m, tm);
        if (mn < -1e29f) continue;   // tile fully masked & no prior keys
        float cr = __expf(m - mn);
        m = mn; ssum *= cr;
        uint64_t cr2 = f2pk(cr, cr);
        #pragma unroll
        for (int j = 0; j < 32; j++) o2[j] = mul2(o2[j], cr2);
        for (int kk = 0; kk < 64; kk++) {
            float p = __expf(sc[kk * 128 + tid] - m);
            ssum += p;
            uint64_t p2 = f2pk(p, p);
            const uint64_t* vr = (const uint64_t*)(Vs + (kk << 6));
            #pragma unroll
            for (int j = 0; j < 32; j++) o2[j] = fma2(p2, vr[j], o2[j]);
        }
    }
    size_t u = (((size_t)(split * 2 + b) * TT + qpos) * HH + h);
    float* op = oP + u * 64;
    #pragma unroll
    for (int j = 0; j < 16; j++) {
        float4 v;
        f2un(o2[2 * j], v.x, v.y);
        f2un(o2[2 * j + 1], v.z, v.w);
        *(float4*)(op + 4 * j) = v;
    }
    msP[u] = make_float2(m, ssum);
}

// merge NSPL softmax partials -> packed fp16 attn out; one warp per (row,h)
__global__ void attn_merge(const float* __restrict__ oP, const float2* __restrict__ msP,
                           uint32_t* __restrict__ attF) {
    int gid = blockIdx.x * 8 + (threadIdx.x >> 5);
    int lane = threadIdx.x & 31;
    int row = gid / HH, h = gid - row * HH;
    int b = row >> 10, q = row & 1023;
    size_t u[NSPL];
    float wgt[NSPL];
    float M = -1e30f;
    float2 ms[NSPL];
    #pragma unroll
    for (int s = 0; s < NSPL; s++) {
        u[s] = (((size_t)(s * 2 + b) * TT + q) * HH + h);
        ms[s] = msP[u[s]];
        if (ms[s].y > 0.f) M = fmaxf(M, ms[s].x);
    }
    float den = 0.f;
    #pragma unroll
    for (int s = 0; s < NSPL; s++) {
        wgt[s] = (ms[s].y > 0.f) ? __expf(ms[s].x - M) : 0.f;
        den += ms[s].y * wgt[s];
    }
    float inv = 1.0f / den;
    float v0 = 0.f, v1 = 0.f;
    #pragma unroll
    for (int s = 0; s < NSPL; s++) {
        if (wgt[s] > 0.f) {
            float2 a = ((const float2*)(oP + u[s] * 64))[lane];
            v0 += a.x * wgt[s];
            v1 += a.y * wgt[s];
        }
    }
    attF[(size_t)row * K2D + h * 32 + lane] = pkh(v0 * inv, v1 * inv);
}

// ---------------- fp16 MMA GEMM (ldmatrix), 128x128, BK=64 --------------
template<int EPI, bool HASBIAS, int TERMS>
__global__ void __launch_bounds__(256, 2)
gemm_lm(const uint32_t* __restrict__ AF, const uint32_t* __restrict__ BhG,
        const uint32_t* __restrict__ BlG, const float* __restrict__ bias,
        float* __restrict__ C, uint32_t* __restrict__ PF,
        int N, int Kslice, int K2s) {
    constexpr int BUFSZ  = (TERMS == 2) ? 49152 : 32768;
    constexpr int STAGES = (TERMS == 2) ? 2 : 3;
    extern __shared__ __align__(16) char smem[];
    uint32_t sbase = (uint32_t)__cvta_generic_to_shared(smem);
    int tid = threadIdx.x;
    int w = tid >> 5, lane = tid & 31;
    int wr = w >> 2, wc = w & 3;
    int q = lane >> 2, r4 = lane & 3;
    int jrow = ((lane >> 3) & 1) * 8 + (lane & 7);
    int gh = lane >> 4;
    int perm = jrow & 7;
    int row0 = blockIdx.x * 128, col0 = blockIdx.y * 128;
    int kofs = blockIdx.z * (Kslice >> 1);

    float acc[4][4][4];
    #pragma unroll
    for (int mi = 0; mi < 4; mi++)
        #pragma unroll
        for (int ni = 0; ni < 4; ni++)
            #pragma unroll
            for (int e = 0; e < 4; e++) acc[mi][ni][e] = 0.f;

    auto loadbuf = [&](int t, int buf) {
        uint32_t base = sbase + buf * BUFSZ;
        int kp0 = kofs + t * 32;
        #pragma unroll
        for (int i = 0; i < 4; i++) {
            int id = tid + i * 256;
            int mm = id >> 3, g = id & 7;
            uint32_t dst = base + (mm << 7) + ((g ^ (mm & 7)) << 4);
            cpa16(dst, AF + (size_t)(row0 + mm) * K2s + kp0 + g * 4);
        }
        #pragma unroll
        for (int i = 0; i < 4; i++) {
            int id = tid + i * 256;
            int nn = id >> 3, g = id & 7;
            uint32_t dst = base + 16384 + (nn << 7) + ((g ^ (nn & 7)) << 4);
            size_t off = (size_t)(col0 + nn) * K2s + kp0 + g * 4;
            cpa16(dst, BhG + off);
            if (TERMS == 2) cpa16(dst + 16384, BlG + off);
        }
    };

    int ntile = Kslice >> 6;
    #pragma unroll
    for (int pt = 0; pt < STAGES - 1; pt++) {
        if (pt < ntile) {
            loadbuf(pt, pt % STAGES);
            asm volatile("cp.async.commit_group;" ::: "memory");
        }
    }
    for (int t = 0; t < ntile; t++) {
        int buf = t % STAGES;
        if (t + STAGES - 1 < ntile) {
            loadbuf(t + STAGES - 1, (t + STAGES - 1) % STAGES);
            asm volatile("cp.async.commit_group;" ::: "memory");
        }
        int p = ntile - t;
        if (STAGES == 3) {
            if (p > 2)      asm volatile("cp.async.wait_group 2;" ::: "memory");
            else if (p > 1) asm volatile("cp.async.wait_group 1;" ::: "memory");
            else            asm volatile("cp.async.wait_group 0;" ::: "memory");
        } else {
            if (p > 1)      asm volatile("cp.async.wait_group 1;" ::: "memory");
            else            asm volatile("cp.async.wait_group 0;" ::: "memory");
        }
        __syncthreads();
        uint32_t base = sbase + buf * BUFSZ;
        #pragma unroll
        for (int s = 0; s < 4; s++) {
            int ks = 2 * s + gh;
            uint32_t ah[4][4], bh[2][4];
            #pragma unroll
            for (int mi = 0; mi < 4; mi++)
                ldsm4(ah[mi], base + ((wr * 64 + mi * 16 + jrow) << 7) + ((ks ^ perm) << 4));
            #pragma unroll
            for (int p2 = 0; p2 < 2; p2++)
                ldsm4(bh[p2], base + 16384 + ((wc * 32 + p2 * 16 + jrow) << 7) + ((ks ^ perm) << 4));
            #pragma unroll
            for (int mi = 0; mi < 4; mi++)
                #pragma unroll
                for (int ni = 0; ni < 4; ni++)
                    mmaf16(acc[mi][ni], ah[mi], bh[ni >> 1][ni & 1], bh[ni >> 1][2 + (ni & 1)]);
            if (TERMS == 2) {
                uint32_t bl[2][4];
                #pragma unroll
                for (int p2 = 0; p2 < 2; p2++)
                    ldsm4(bl[p2], base + 32768 + ((wc * 32 + p2 * 16 + jrow) << 7) + ((ks ^ perm) << 4));
                #pragma unroll
                for (int mi = 0; mi < 4; mi++)
                    #pragma unroll
                    for (int ni = 0; ni < 4; ni++)
                        mmaf16(acc[mi][ni], ah[mi], bl[ni >> 1][ni & 1], bl[ni >> 1][2 + (ni & 1)]);
            }
        }
        __syncthreads();
    }

    const float cg = 0.7978845608028654f;
    #pragma unroll
    for (int mi = 0; mi < 4; mi++) {
        int rbase = row0 + wr * 64 + mi * 16 + q;
        #pragma unroll
        for (int ni = 0; ni < 4; ni++) {
            int cbase = col0 + wc * 32 + ni * 8 + 2 * r4;
            #pragma unroll
            for (int rg = 0; rg < 2; rg++) {
                int rr = rbase + rg * 8;
                float v0 = acc[mi][ni][rg * 2 + 0] * 0.00390625f;
                float v1 = acc[mi][ni][rg * 2 + 1] * 0.00390625f;
                if (HASBIAS) { v0 += bias[cbase]; v1 += bias[cbase + 1]; }
                if (EPI == 2) {
                    float u0 = cg * (v0 + 0.044715f * v0 * v0 * v0);
                    v0 = 0.5f * v0 * (1.0f + tanhf(u0));
                    float u1 = cg * (v1 + 0.044715f * v1 * v1 * v1);
                    v1 = 0.5f * v1 * (1.0f + tanhf(u1));
                    PF[(size_t)rr * (N >> 1) + (cbase >> 1)] = pkh(v0, v1);
                } else if (EPI == 3) {
                    size_t idx = ((size_t)blockIdx.z * NT + rr) * N + cbase;
                    C[idx] = v0;
                    C[idx + 1] = v1;
                } else {
                    size_t idx = (size_t)rr * N + cbase;
                    if (cbase < N) C[idx] = v0;
                    if (cbase + 1 < N) C[idx + 1] = v1;
                }
            }
        }
    }
}

#define GSM1 98304

// ---------------- host ----------------
extern "C" void kernel_launch(void* const* d_in, const int* in_sizes, int n_in,
                              void* d_out, int out_size) {
    const int*   tok    = (const int*)  d_in[0];
    const float* wte    = (const float*)d_in[1];
    const float* wpe    = (const float*)d_in[2];
    const float* ln1_w  = (const float*)d_in[3];
    const float* ln1_b  = (const float*)d_in[4];
    const float* attn_w = (const float*)d_in[5];
    const float* attn_b = (const float*)d_in[6];
    const float* proj_w = (const float*)d_in[7];
    const float* proj_b = (const float*)d_in[8];
    const float* ln2_w  = (const float*)d_in[9];
    const float* ln2_b  = (const float*)d_in[10];
    const float* fc_w   = (const float*)d_in[11];
    const float* fc_b   = (const float*)d_in[12];
    const float* fc2_w  = (const float*)d_in[13];
    const float* fc2_b  = (const float*)d_in[14];
    const float* lnf_w  = (const float*)d_in[15];
    const float* lnf_b  = (const float*)d_in[16];
    const float* head_w = (const float*)d_in[17];
    float* out = (float*)d_out;

    float *x, *qkv, *oP;
    uint32_t *hF, *atF, *ffF;
    float2* attms;
    cudaGetSymbolAddress((void**)&x, g_x);
    cudaGetSymbolAddress((void**)&qkv, g_qkv);
    cudaGetSymbolAddress((void**)&hF, g_hF);
    cudaGetSymbolAddress((void**)&atF, g_atF);
    cudaGetSymbolAddress((void**)&ffF, g_ffF);
    cudaGetSymbolAddress((void**)&oP, g_oP);
    cudaGetSymbolAddress((void**)&attms, g_attms);
    uint32_t *wq_h, *wq_l, *wp_h, *wp_l, *wf_h, *wf_l, *w2_h, *w2_l, *wh_h;
    cudaGetSymbolAddress((void**)&wq_h, g_wq_h);
    cudaGetSymbolAddress((void**)&wq_l, g_wq_l);
    cudaGetSymbolAddress((void**)&wp_h, g_wp_h);
    cudaGetSymbolAddress((void**)&wp_l, g_wp_l);
    cudaGetSymbolAddress((void**)&wf_h, g_wf_h);
    cudaGetSymbolAddress((void**)&wf_l, g_wf_l);
    cudaGetSymbolAddress((void**)&w2_h, g_w2_h);
    cudaGetSymbolAddress((void**)&w2_l, g_w2_l);
    cudaGetSymbolAddress((void**)&wh_h, g_wh_h);

    cudaFuncSetAttribute(gemm_lm<0, true,  1>, cudaFuncAttributeMaxDynamicSharedMemorySize, GSM1);
    cudaFuncSetAttribute(gemm_lm<2, true,  1>, cudaFuncAttributeMaxDynamicSharedMemorySize, GSM1);
    cudaFuncSetAttribute(gemm_lm<3, false, 1>, cudaFuncAttributeMaxDynamicSharedMemorySize, GSM1);
    cudaFuncSetAttribute(gemm_lm<0, false, 1>, cudaFuncAttributeMaxDynamicSharedMemorySize, GSM1);
    cudaFuncSetAttribute(attn_split, cudaFuncAttributeMaxDynamicSharedMemorySize, 65536);

    pack_w_t<<<dim3(12, 72, LL), 256>>>(attn_w, wq_h, wq_l, DD, D3);
    pack_w_t<<<dim3(12, 24, LL), 256>>>(proj_w, wp_h, wp_l, DD, DD);
    pack_w_t<<<dim3(12, 96, LL), 256>>>(fc_w,  wf_h, wf_l, DD, FF);
    pack_w_t<<<dim3(48, 24, LL), 256>>>(fc2_w, w2_h, w2_l, FF, DD);
    pack_headf<<<(VP * K2D + 255) / 256, 256>>>(head_w, wh_h);

    embed_ln_pack<<<NT, 256>>>(tok, wte, wpe, x, ln1_w, ln1_b, hF);

    for (int l = 0; l < LL; l++) {
        size_t oq = (size_t)l * D3 * K2D, op = (size_t)l * DD * K2D;
        size_t of = (size_t)l * FF * K2D, o2 = (size_t)l * DD * K2F;

        gemm_lm<0, true, 1><<<dim3(NT / 128, D3 / 128, 1), 256, GSM1>>>(
            hF, wq_h + oq, wq_l + oq, attn_b + l * D3, qkv, nullptr, D3, DD, K2D);
        attn_split<<<dim3(TT / 128, HH * NSPL, 2), 128, 65536>>>(qkv, oP, attms);
        attn_merge<<<NT * HH / 8, 256>>>(oP, attms, atF);
        gemm_lm<3, false, 1><<<dim3(NT / 128, DD / 128, 3), 256, GSM1>>>(
            atF, wp_h + op, wp_l + op, nullptr, qkv, nullptr, DD, DD / 3, K2D);
        red_ln_pack<<<NT, 256>>>(qkv, proj_b + l * DD, x, ln2_w + l * DD, ln2_b + l * DD, hF);
        gemm_lm<2, true, 1><<<dim3(NT / 128, FF / 128, 1), 256, GSM1>>>(
            hF, wf_h + of, wf_l + of, fc_b + l * FF, nullptr, ffF, FF, DD, K2D);
        gemm_lm<3, false, 1><<<dim3(NT / 128, DD / 128, 3), 256, GSM1>>>(
            ffF, w2_h + o2, w2_l + o2, nullptr, qkv, nullptr, DD, FF / 3, K2F);
        const float* nw = (l < LL - 1) ? ln1_w + (l + 1) * DD : lnf_w;
        const float* nb = (l < LL - 1) ? ln1_b + (l + 1) * DD : lnf_b;
        red_ln_pack<<<NT, 256>>>(qkv, fc2_b + l * DD, x, nw, nb, hF);
    }

    gemm_lm<0, false, 1><<<dim3(NT / 128, VP / 128, 1), 256, GSM1>>>(
        hF, wh_h, nullptr, nullptr, out, nullptr, VV, DD, K2D);
}

// round 16
// speedup vs baseline: 1.0275x; 1.0275x over previous
#include <cuda_runtime.h>
#include <cuda_bf16.h>
#include <cuda_fp16.h>
#include <math.h>
#include <stdint.h>

#define NT 2048
#define TT 1024
#define DD 768
#define FF 3072
#define HH 12
#define HD 64
#define LL 4
#define VV 50257
#define D3 2304
#define VP 50304
#define K2D 384
#define K2F 1536
#define NSPL 4

// ---------------- scratch ----------------
__device__ float    g_x[NT * DD];
__device__ float    g_qkv[NT * D3];   // also split-K partial buffer [3][NT][DD]
__device__ uint32_t g_hF[NT * K2D];
__device__ uint32_t g_atF[NT * K2D];
__device__ uint32_t g_ffF[NT * K2F];
__device__ float    g_oP[NSPL * NT * HH * 64];      // attention o-partials
__device__ float2   g_attms[NSPL * NT * HH];        // (m, ssum)
// weights n-major [N][K/2] fp16-pair words, scaled x256, hi/lo
__device__ uint32_t g_wq_h[LL * D3 * K2D], g_wq_l[LL * D3 * K2D];
__device__ uint32_t g_wp_h[LL * DD * K2D], g_wp_l[LL * DD * K2D];
__device__ uint32_t g_wf_h[LL * FF * K2D], g_wf_l[LL * FF * K2D];
__device__ uint32_t g_w2_h[LL * DD * K2F], g_w2_l[LL * DD * K2F];
__device__ uint32_t g_wh_h[VP * K2D];

// ---------------- helpers ----------------
__device__ __forceinline__ uint32_t pkh(float x, float y) {
    __half hx = __float2half_rn(x), hy = __float2half_rn(y);
    return ((uint32_t)__half_as_ushort(hy) << 16) | (uint32_t)__half_as_ushort(hx);
}
__device__ __forceinline__ void cvt2h(float x, float y, uint32_t& hi, uint32_t& lo) {
    __half hx = __float2half_rn(x), hy = __float2half_rn(y);
    hi = ((uint32_t)__half_as_ushort(hy) << 16) | (uint32_t)__half_as_ushort(hx);
    lo = pkh(x - __half2float(hx), y - __half2float(hy));
}
__device__ __forceinline__ void cpa16(uint32_t d, const void* s) {
    asm volatile("cp.async.cg.shared.global [%0], [%1], 16;" :: "r"(d), "l"(s));
}
__device__ __forceinline__ void ldsm4(uint32_t* r, uint32_t a) {
    asm volatile("ldmatrix.sync.aligned.m8n8.x4.shared.b16 {%0,%1,%2,%3}, [%4];"
                 : "=r"(r[0]), "=r"(r[1]), "=r"(r[2]), "=r"(r[3]) : "r"(a));
}
__device__ __forceinline__ void mmaf16(float* c, const uint32_t* a, uint32_t b0, uint32_t b1) {
    asm volatile("mma.sync.aligned.m16n8k16.row.col.f32.f16.f16.f32 "
                 "{%0,%1,%2,%3}, {%4,%5,%6,%7}, {%8,%9}, {%0,%1,%2,%3};\n"
                 : "+f"(c[0]), "+f"(c[1]), "+f"(c[2]), "+f"(c[3])
                 : "r"(a[0]), "r"(a[1]), "r"(a[2]), "r"(a[3]), "r"(b0), "r"(b1));
}
__device__ __forceinline__ uint64_t f2pk(float x, float y) {
    uint64_t r; asm("mov.b64 %0, {%1,%2};" : "=l"(r) : "f"(x), "f"(y)); return r;
}
__device__ __forceinline__ void f2un(uint64_t v, float& x, float& y) {
    asm("mov.b64 {%0,%1}, %2;" : "=f"(x), "=f"(y) : "l"(v));
}
__device__ __forceinline__ uint64_t fma2(uint64_t a, uint64_t b, uint64_t c) {
    uint64_t d; asm("fma.rn.f32x2 %0, %1, %2, %3;" : "=l"(d) : "l"(a), "l"(b), "l"(c)); return d;
}
__device__ __forceinline__ uint64_t mul2(uint64_t a, uint64_t b) {
    uint64_t d; asm("mul.rn.f32x2 %0, %1, %2;" : "=l"(d) : "l"(a), "l"(b)); return d;
}

// ---------------- packing ----------------
__global__ void pack_w_t(const float* __restrict__ W, uint32_t* __restrict__ Oh,
                         uint32_t* __restrict__ Ol, int K, int N) {
    __shared__ float s[64][33];
    int K2 = K >> 1;
    const float* Wl = W + (size_t)blockIdx.z * K * N;
    uint32_t* OhL = Oh + (size_t)blockIdx.z * N * K2;
    uint32_t* OlL = Ol + (size_t)blockIdx.z * N * K2;
    int k0 = blockIdx.x * 64, n0 = blockIdx.y * 32;
    int rr = threadIdx.x >> 5, cc = threadIdx.x & 31;
    #pragma unroll
    for (int i = 0; i < 8; i++)
        s[rr + i * 8][cc] = Wl[(size_t)(k0 + rr + i * 8) * N + n0 + cc];
    __syncthreads();
    #pragma unroll
    for (int i = 0; i < 4; i++) {
        int n = rr + i * 8;
        uint32_t h, l;
        cvt2h(s[2 * cc][n] * 256.f, s[2 * cc + 1][n] * 256.f, h, l);
        OhL[(size_t)(n0 + n) * K2 + (k0 >> 1) + cc] = h;
        OlL[(size_t)(n0 + n) * K2 + (k0 >> 1) + cc] = l;
    }
}
__global__ void pack_headf(const float* __restrict__ W, uint32_t* __restrict__ Oh) {
    int id = blockIdx.x * 256 + threadIdx.x;
    if (id >= VP * K2D) return;
    int n = id / K2D, kp = id - n * K2D;
    float x = 0.f, y = 0.f;
    if (n < VV) { const float* p = W + (size_t)n * DD + 2 * kp; x = p[0] * 256.f; y = p[1] * 256.f; }
    Oh[id] = pkh(x, y);
}

// ---------------- LN machinery ----------------
__device__ __forceinline__ float blk_sum(float v, float* red) {
    #pragma unroll
    for (int o = 16; o; o >>= 1) v += __shfl_xor_sync(0xffffffffu, v, o);
    if ((threadIdx.x & 31) == 0) red[threadIdx.x >> 5] = v;
    __syncthreads();
    float s = (threadIdx.x < 8) ? red[threadIdx.x] : 0.0f;
    #pragma unroll
    for (int o = 4; o; o >>= 1) s += __shfl_xor_sync(0xffffffffu, s, o);
    if (threadIdx.x == 0) red[0] = s;
    __syncthreads();
    s = red[0];
    __syncthreads();
    return s;
}

__device__ __forceinline__ void ln_body(float* v, float s, float ss, float* vb,
                                        const float* w, const float* b, int row,
                                        uint32_t* PF) {
    float mu = s * (1.0f / DD);
    float r = rsqrtf(ss * (1.0f / DD) - mu * mu + 1e-5f);
    #pragma unroll
    for (int i = 0; i < 3; i++) {
        int c = threadIdx.x + i * 256;
        vb[c] = (v[i] - mu) * r * w[c] + b[c];
    }
    __syncthreads();
    #pragma unroll
    for (int i = 0; i < 2; i++) {
        int p = threadIdx.x + i * 256;
        if (p < K2D)
            PF[(size_t)row * K2D + p] = pkh(vb[2 * p], vb[2 * p + 1]);
    }
}

__global__ void embed_ln_pack(const int* __restrict__ tok, const float* __restrict__ wte,
                              const float* __restrict__ wpe, float* __restrict__ x,
                              const float* __restrict__ w, const float* __restrict__ b,
                              uint32_t* __restrict__ PF) {
    __shared__ float vb[DD];
    __shared__ float red[32];
    int row = blockIdx.x, t = tok[row];
    const float* we = wte + (size_t)t * DD;
    const float* wp = wpe + (size_t)(row & (TT - 1)) * DD;
    float v[3], s = 0.f, ss = 0.f;
    #pragma unroll
    for (int i = 0; i < 3; i++) {
        int c = threadIdx.x + i * 256;
        v[i] = we[c] + wp[c];
        x[(size_t)row * DD + c] = v[i];
        s += v[i]; ss += v[i] * v[i];
    }
    s = blk_sum(s, red); ss = blk_sum(ss, red);
    ln_body(v, s, ss, vb, w, b, row, PF);
}

__global__ void red_ln_pack(const float* __restrict__ P, const float* __restrict__ bias,
                            float* __restrict__ x, const float* __restrict__ w,
                            const float* __restrict__ b, uint32_t* __restrict__ PF) {
    __shared__ float vb[DD];
    __shared__ float red[32];
    int row = blockIdx.x;
    float v[3], s = 0.f, ss = 0.f;
    #pragma unroll
    for (int i = 0; i < 3; i++) {
        int c = threadIdx.x + i * 256;
        size_t idx = (size_t)row * DD + c;
        float t = x[idx] + bias[c] + P[idx] + P[(size_t)NT * DD + idx] + P[2 * (size_t)NT * DD + idx];
        x[idx] = t;
        v[i] = t; s += t; ss += t * t;
    }
    s = blk_sum(s, red); ss = blk_sum(ss, red);
    ln_body(v, s, ss, vb, w, b, row, PF);
}

// ---------------- attention: split-KV (4-way) ----------------
__global__ void __launch_bounds__(128)
attn_split(const float* __restrict__ qkv, float* __restrict__ oP,
           float2* __restrict__ msP) {
    extern __shared__ __align__(16) unsigned sm_dyn[];
    float* Ks = (float*)sm_dyn;
    float* Vs = Ks + 4096;
    float* sc = Vs + 4096;
    int tid = threadIdx.x;
    int qt = blockIdx.x;
    int h = blockIdx.y >> 2, split = blockIdx.y & 3;
    int b = blockIdx.z;
    int qpos = qt * 128 + tid;
    const float* base = qkv + (size_t)b * TT * D3;
    uint64_t q2[32], o2[32];
    {
        const float* qp = base + (size_t)qpos * D3 + h * HD;
        #pragma unroll
        for (int j = 0; j < 32; j++) q2[j] = f2pk(qp[2 * j], qp[2 * j + 1]);
    }
    #pragma unroll
    for (int j = 0; j < 32; j++) o2[j] = 0ull;
    float m = -1e30f, ssum = 0.f;
    int nkt = (qt + 1) * 2;
    for (int kt = split; kt < nkt; kt += NSPL) {
        int k0 = kt * 64;
        __syncthreads();
        #pragma unroll
        for (int i = 0; i < 8; i++) {
            int idx = (i * 128 + tid) * 4;
            int kk = idx >> 6, e = idx & 63;
            const float* rowp = base + (size_t)(k0 + kk) * D3 + h * HD + e;
            *(float4*)(Ks + idx) = *(const float4*)(rowp + DD);
            *(float4*)(Vs + idx) = *(const float4*)(rowp + 2 * DD);
        }
        __syncthreads();
        float tm = -1e30f;
        for (int kk = 0; kk < 64; kk++) {
            const uint64_t* kr = (const uint64_t*)(Ks + (kk << 6));
            uint64_t a0 = 0ull, a1 = 0ull, a2 = 0ull, a3 = 0ull;
            #pragma unroll
            for (int j = 0; j < 32; j += 4) {
                a0 = fma2(q2[j], kr[j], a0);
                a1 = fma2(q2[j + 1], kr[j + 1], a1);
                a2 = fma2(q2[j + 2], kr[j + 2], a2);
                a3 = fma2(q2[j + 3], kr[j + 3], a3);
            }
            float x0, y0, x1, y1, x2, y2, x3, y3;
            f2un(a0, x0, y0); f2un(a1, x1, y1); f2un(a2, x2, y2); f2un(a3, x3, y3);
            float sv = (((x0 + y0) + (x1 + y1)) + ((x2 + y2) + (x3 + y3))) * 0.125f;
            if (k0 + kk > qpos) sv = -1e30f;
            sc[kk * 128 + tid] = sv;
            tm = fmaxf(tm, sv);
        }
        float mn = fmaxf(m, tm);
        if (mn < -1e29f) continue;   // tile fully masked & no prior keys
        float cr = __expf(m - mn);
        m = mn; ssum *= cr;
        uint64_t cr2 = f2pk(cr, cr);
        #pragma unroll
        for (int j = 0; j < 32; j++) o2[j] = mul2(o2[j], cr2);
        for (int kk = 0; kk < 64; kk++) {
            float p = __expf(sc[kk * 128 + tid] - m);
            ssum += p;
            uint64_t p2 = f2pk(p, p);
            const uint64_t* vr = (const uint64_t*)(Vs + (kk << 6));
            #pragma unroll
            for (int j = 0; j < 32; j++) o2[j] = fma2(p2, vr[j], o2[j]);
        }
    }
    size_t u = (((size_t)(split * 2 + b) * TT + qpos) * HH + h);
    float* op = oP + u * 64;
    #pragma unroll
    for (int j = 0; j < 16; j++) {
        float4 v;
        f2un(o2[2 * j], v.x, v.y);
        f2un(o2[2 * j + 1], v.z, v.w);
        *(float4*)(op + 4 * j) = v;
    }
    msP[u] = make_float2(m, ssum);
}

// merge NSPL softmax partials -> packed fp16 attn out; one warp per (row,h)
__global__ void attn_merge(const float* __restrict__ oP, const float2* __restrict__ msP,
                           uint32_t* __restrict__ attF) {
    int gid = blockIdx.x * 8 + (threadIdx.x >> 5);
    int lane = threadIdx.x & 31;
    int row = gid / HH, h = gid - row * HH;
    int b = row >> 10, q = row & 1023;
    size_t u[NSPL];
    float wgt[NSPL];
    float M = -1e30f;
    float2 ms[NSPL];
    #pragma unroll
    for (int s = 0; s < NSPL; s++) {
        u[s] = (((size_t)(s * 2 + b) * TT + q) * HH + h);
        ms[s] = msP[u[s]];
        if (ms[s].y > 0.f) M = fmaxf(M, ms[s].x);
    }
    float den = 0.f;
    #pragma unroll
    for (int s = 0; s < NSPL; s++) {
        wgt[s] = (ms[s].y > 0.f) ? __expf(ms[s].x - M) : 0.f;
        den += ms[s].y * wgt[s];
    }
    float inv = 1.0f / den;
    float v0 = 0.f, v1 = 0.f;
    #pragma unroll
    for (int s = 0; s < NSPL; s++) {
        if (wgt[s] > 0.f) {
            float2 a = ((const float2*)(oP + u[s] * 64))[lane];
            v0 += a.x * wgt[s];
            v1 += a.y * wgt[s];
        }
    }
    attF[(size_t)row * K2D + h * 32 + lane] = pkh(v0 * inv, v1 * inv);
}

// -------- fp16 MMA GEMM (ldmatrix), 128x128, BK=64, 3-stage, 1 barrier/tile
// A fp16 pairs [M][K/2]; B fp16 n-major [N][K/2] (x256).
// EPI: 0 store fp32 (+bias), 2 bias+GELU->fp16, 3 split-K partial.
#define BUFSZ 32768
#define GSM1  98304

template<int EPI, bool HASBIAS>
__global__ void __launch_bounds__(256, 2)
gemm_lm(const uint32_t* __restrict__ AF, const uint32_t* __restrict__ BhG,
        const float* __restrict__ bias,
        float* __restrict__ C, uint32_t* __restrict__ PF,
        int N, int Kslice, int K2s) {
    extern __shared__ __align__(16) char smem[];
    uint32_t sbase = (uint32_t)__cvta_generic_to_shared(smem);
    int tid = threadIdx.x;
    int w = tid >> 5, lane = tid & 31;
    int wr = w >> 2, wc = w & 3;
    int q = lane >> 2, r4 = lane & 3;
    int jrow = ((lane >> 3) & 1) * 8 + (lane & 7);
    int gh = lane >> 4;
    int perm = jrow & 7;
    int row0 = blockIdx.x * 128, col0 = blockIdx.y * 128;
    int kofs = blockIdx.z * (Kslice >> 1);

    float acc[4][4][4];
    #pragma unroll
    for (int mi = 0; mi < 4; mi++)
        #pragma unroll
        for (int ni = 0; ni < 4; ni++)
            #pragma unroll
            for (int e = 0; e < 4; e++) acc[mi][ni][e] = 0.f;

    auto loadbuf = [&](int t, int buf) {
        uint32_t base = sbase + buf * BUFSZ;
        int kp0 = kofs + t * 32;
        #pragma unroll
        for (int i = 0; i < 4; i++) {
            int id = tid + i * 256;
            int mm = id >> 3, g = id & 7;
            uint32_t dst = base + (mm << 7) + ((g ^ (mm & 7)) << 4);
            cpa16(dst, AF + (size_t)(row0 + mm) * K2s + kp0 + g * 4);
        }
        #pragma unroll
        for (int i = 0; i < 4; i++) {
            int id = tid + i * 256;
            int nn = id >> 3, g = id & 7;
            uint32_t dst = base + 16384 + (nn << 7) + ((g ^ (nn & 7)) << 4);
            cpa16(dst, BhG + (size_t)(col0 + nn) * K2s + kp0 + g * 4);
        }
    };

    int ntile = Kslice >> 6;   // >= 4 for all our shapes
    loadbuf(0, 0);
    asm volatile("cp.async.commit_group;" ::: "memory");
    loadbuf(1, 1);
    asm volatile("cp.async.commit_group;" ::: "memory");

    for (int t = 0; t < ntile; t++) {
        if (t + 1 < ntile) asm volatile("cp.async.wait_group 1;" ::: "memory");
        else               asm volatile("cp.async.wait_group 0;" ::: "memory");
        __syncthreads();
        // safe: buffer (t+2)%3 was consumed at iter t-1; everyone passed the barrier
        if (t + 2 < ntile) {
            loadbuf(t + 2, (t + 2) % 3);
            asm volatile("cp.async.commit_group;" ::: "memory");
        }
        uint32_t base = sbase + (t % 3) * BUFSZ;
        #pragma unroll
        for (int s = 0; s < 4; s++) {
            int ks = 2 * s + gh;
            uint32_t ah[4][4], bh[2][4];
            #pragma unroll
            for (int mi = 0; mi < 4; mi++)
                ldsm4(ah[mi], base + ((wr * 64 + mi * 16 + jrow) << 7) + ((ks ^ perm) << 4));
            #pragma unroll
            for (int p2 = 0; p2 < 2; p2++)
                ldsm4(bh[p2], base + 16384 + ((wc * 32 + p2 * 16 + jrow) << 7) + ((ks ^ perm) << 4));
            #pragma unroll
            for (int mi = 0; mi < 4; mi++)
                #pragma unroll
                for (int ni = 0; ni < 4; ni++)
                    mmaf16(acc[mi][ni], ah[mi], bh[ni >> 1][ni & 1], bh[ni >> 1][2 + (ni & 1)]);
        }
    }

    const float cg = 0.7978845608028654f;
    #pragma unroll
    for (int mi = 0; mi < 4; mi++) {
        int rbase = row0 + wr * 64 + mi * 16 + q;
        #pragma unroll
        for (int ni = 0; ni < 4; ni++) {
            int cbase = col0 + wc * 32 + ni * 8 + 2 * r4;
            #pragma unroll
            for (int rg = 0; rg < 2; rg++) {
                int rr = rbase + rg * 8;
                float v0 = acc[mi][ni][rg * 2 + 0] * 0.00390625f;
                float v1 = acc[mi][ni][rg * 2 + 1] * 0.00390625f;
                if (HASBIAS) { v0 += bias[cbase]; v1 += bias[cbase + 1]; }
                if (EPI == 2) {
                    float u0 = cg * (v0 + 0.044715f * v0 * v0 * v0);
                    v0 = 0.5f * v0 * (1.0f + tanhf(u0));
                    float u1 = cg * (v1 + 0.044715f * v1 * v1 * v1);
                    v1 = 0.5f * v1 * (1.0f + tanhf(u1));
                    PF[(size_t)rr * (N >> 1) + (cbase >> 1)] = pkh(v0, v1);
                } else if (EPI == 3) {
                    size_t idx = ((size_t)blockIdx.z * NT + rr) * N + cbase;
                    C[idx] = v0;
                    C[idx + 1] = v1;
                } else {
                    size_t idx = (size_t)rr * N + cbase;
                    if (cbase < N) C[idx] = v0;
                    if (cbase + 1 < N) C[idx + 1] = v1;
                }
            }
        }
    }
}

// ---------------- host ----------------
extern "C" void kernel_launch(void* const* d_in, const int* in_sizes, int n_in,
                              void* d_out, int out_size) {
    const int*   tok    = (const int*)  d_in[0];
    const float* wte    = (const float*)d_in[1];
    const float* wpe    = (const float*)d_in[2];
    const float* ln1_w  = (const float*)d_in[3];
    const float* ln1_b  = (const float*)d_in[4];
    const float* attn_w = (const float*)d_in[5];
    const float* attn_b = (const float*)d_in[6];
    const float* proj_w = (const float*)d_in[7];
    const float* proj_b = (const float*)d_in[8];
    const float* ln2_w  = (const float*)d_in[9];
    const float* ln2_b  = (const float*)d_in[10];
    const float* fc_w   = (const float*)d_in[11];
    const float* fc_b   = (const float*)d_in[12];
    const float* fc2_w  = (const float*)d_in[13];
    const float* fc2_b  = (const float*)d_in[14];
    const float* lnf_w  = (const float*)d_in[15];
    const float* lnf_b  = (const float*)d_in[16];
    const float* head_w = (const float*)d_in[17];
    float* out = (float*)d_out;

    float *x, *qkv, *oP;
    uint32_t *hF, *atF, *ffF;
    float2* attms;
    cudaGetSymbolAddress((void**)&x, g_x);
    cudaGetSymbolAddress((void**)&qkv, g_qkv);
    cudaGetSymbolAddress((void**)&hF, g_hF);
    cudaGetSymbolAddress((void**)&atF, g_atF);
    cudaGetSymbolAddress((void**)&ffF, g_ffF);
    cudaGetSymbolAddress((void**)&oP, g_oP);
    cudaGetSymbolAddress((void**)&attms, g_attms);
    uint32_t *wq_h, *wq_l, *wp_h, *wp_l, *wf_h, *wf_l, *w2_h, *w2_l, *wh_h;
    cudaGetSymbolAddress((void**)&wq_h, g_wq_h);
    cudaGetSymbolAddress((void**)&wq_l, g_wq_l);
    cudaGetSymbolAddress((void**)&wp_h, g_wp_h);
    cudaGetSymbolAddress((void**)&wp_l, g_wp_l);
    cudaGetSymbolAddress((void**)&wf_h, g_wf_h);
    cudaGetSymbolAddress((void**)&wf_l, g_wf_l);
    cudaGetSymbolAddress((void**)&w2_h, g_w2_h);
    cudaGetSymbolAddress((void**)&w2_l, g_w2_l);
    cudaGetSymbolAddress((void**)&wh_h, g_wh_h);

    cudaFuncSetAttribute(gemm_lm<0, true >, cudaFuncAttributeMaxDynamicSharedMemorySize, GSM1);
    cudaFuncSetAttribute(gemm_lm<2, true >, cudaFuncAttributeMaxDynamicSharedMemorySize, GSM1);
    cudaFuncSetAttribute(gemm_lm<3, false>, cudaFuncAttributeMaxDynamicSharedMemorySize, GSM1);
    cudaFuncSetAttribute(gemm_lm<0, false>, cudaFuncAttributeMaxDynamicSharedMemorySize, GSM1);
    cudaFuncSetAttribute(attn_split, cudaFuncAttributeMaxDynamicSharedMemorySize, 65536);

    pack_w_t<<<dim3(12, 72, LL), 256>>>(attn_w, wq_h, wq_l, DD, D3);
    pack_w_t<<<dim3(12, 24, LL), 256>>>(proj_w, wp_h, wp_l, DD, DD);
    pack_w_t<<<dim3(12, 96, LL), 256>>>(fc_w,  wf_h, wf_l, DD, FF);
    pack_w_t<<<dim3(48, 24, LL), 256>>>(fc2_w, w2_h, w2_l, FF, DD);
    pack_headf<<<(VP * K2D + 255) / 256, 256>>>(head_w, wh_h);

    embed_ln_pack<<<NT, 256>>>(tok, wte, wpe, x, ln1_w, ln1_b, hF);

    for (int l = 0; l < LL; l++) {
        size_t oq = (size_t)l * D3 * K2D, op = (size_t)l * DD * K2D;
        size_t of = (size_t)l * FF * K2D, o2 = (size_t)l * DD * K2F;

        gemm_lm<0, true><<<dim3(NT / 128, D3 / 128, 1), 256, GSM1>>>(
            hF, wq_h + oq, attn_b + l * D3, qkv, nullptr, D3, DD, K2D);
        attn_split<<<dim3(TT / 128, HH * NSPL, 2), 128, 65536>>>(qkv, oP, attms);
        attn_merge<<<NT * HH / 8, 256>>>(oP, attms, atF);
        gemm_lm<3, false><<<dim3(NT / 128, DD / 128, 3), 256, GSM1>>>(
            atF, wp_h + op, nullptr, qkv, nullptr, DD, DD / 3, K2D);
        red_ln_pack<<<NT, 256>>>(qkv, proj_b + l * DD, x, ln2_w + l * DD, ln2_b + l * DD, hF);
        gemm_lm<2, true><<<dim3(NT / 128, FF / 128, 1), 256, GSM1>>>(
            hF, wf_h + of, fc_b + l * FF, nullptr, ffF, FF, DD, K2D);
        gemm_lm<3, false><<<dim3(NT / 128, DD / 128, 3), 256, GSM1>>>(
            ffF, w2_h + o2, nullptr, qkv, nullptr, DD, FF / 3, K2F);
        const float* nw = (l < LL - 1) ? ln1_w + (l + 1) * DD : lnf_w;
        const float* nb = (l < LL - 1) ? ln1_b + (l + 1) * DD : lnf_b;
        red_ln_pack<<<NT, 256>>>(qkv, fc2_b + l * DD, x, nw, nb, hF);
    }

    gemm_lm<0, false><<<dim3(NT / 128, VP / 128, 1), 256, GSM1>>>(
        hF, wh_h, nullptr, out, nullptr, VV, DD, K2D);
}